// round 11
// baseline (speedup 1.0000x reference)
#include <cuda_runtime.h>
#include <cuda_fp16.h>
#include <cstdint>

// ---------------- problem constants ----------------
#define BB 8
#define TT 100
#define SS 400
#define KK 8
#define HH 512
#define VV 32000
#define MMROWS 800
#define MPAD 896

// fp16 operands (single GEMM, K=512)
__device__ __half d_A2[(size_t)MPAD * HH];        // 0.92 MB (pad rows stay zero-init)
__device__ __half d_B2[(size_t)HH * VV];          // 32.8 MB (fits in L2)
__device__ __half d_logits[(size_t)MMROWS * VV];  // 51.2 MB fp16 logits
__device__ float  d_sumexp[MMROWS];               // per-row sum of exp(logit)

static __device__ __forceinline__ uint32_t pack_h2(__half a, __half b) {
    return (uint32_t)__half_as_ushort(a) | ((uint32_t)__half_as_ushort(b) << 16);
}

__global__ __launch_bounds__(256)
void zero_sumexp() {
    const int i = blockIdx.x * 256 + threadIdx.x;
    if (i < MMROWS) d_sumexp[i] = 0.f;
}

// ---------------- conversion: A -> fp16 ----------------
__global__ __launch_bounds__(256)
void conv_a_kernel(const float* __restrict__ A) {
    const int idx = blockIdx.x * 256 + threadIdx.x;      // 800*128
    if (idx >= MMROWS * 128) return;
    const int row = idx >> 7;
    const int kq = idx & 127;
    const float4 v = *(const float4*)(A + (size_t)row * HH + kq * 4);
    uint2 p;
    p.x = pack_h2(__float2half_rn(v.x), __float2half_rn(v.y));
    p.y = pack_h2(__float2half_rn(v.z), __float2half_rn(v.w));
    *(uint2*)(d_A2 + (size_t)row * HH + kq * 4) = p;
}

// ---------------- conversion: W -> fp16 ----------------
__global__ __launch_bounds__(256)
void conv_b_kernel(const float* __restrict__ W) {
    const int idx = blockIdx.x * 256 + threadIdx.x;      // 512*8000
    if (idx >= HH * (VV / 4)) return;
    const float4 v = *(const float4*)(W + (size_t)idx * 4);
    uint2 p;
    p.x = pack_h2(__float2half_rn(v.x), __float2half_rn(v.y));
    p.y = pack_h2(__float2half_rn(v.z), __float2half_rn(v.w));
    *(uint2*)(d_B2 + (size_t)idx * 4) = p;
}

// ---------------- mma.sync GEMM + fused row-sumexp ----------------
// CTA 128x128, 128 threads = 4 warps (2x2), warp tile 64x64, 4-stage pipeline,
// fragment-level software pipelining (all LDSM issued before MMA bursts).
#define BM 128
#define BN 128
#define BK 32
#define STAGES 4
#define KTILES (HH / BK)             // 16
#define A_STRIDE 40                  // halves/row (32 + 8 pad) -> 80 B
#define B_STRIDE 136                 // halves/row (128 + 8 pad) -> 272 B
#define A_BYTES (BM * A_STRIDE * 2)  // 10240
#define B_BYTES (BK * B_STRIDE * 2)  // 8704
#define STAGE_BYTES (A_BYTES + B_BYTES)  // 18944
#define GEMM_SMEM (STAGES * STAGE_BYTES) // 75776

__device__ __forceinline__ uint32_t smem_u32(const void* p) {
    uint32_t a;
    asm("{ .reg .u64 t; cvta.to.shared.u64 t, %1; cvt.u32.u64 %0, t; }" : "=r"(a) : "l"(p));
    return a;
}
__device__ __forceinline__ void cp16(uint32_t dst, const void* src) {
    asm volatile("cp.async.cg.shared.global [%0], [%1], 16;" :: "r"(dst), "l"(src) : "memory");
}
__device__ __forceinline__ void cp_commit() {
    asm volatile("cp.async.commit_group;" ::: "memory");
}
__device__ __forceinline__ void cp_wait2() {
    asm volatile("cp.async.wait_group 2;" ::: "memory");
}
__device__ __forceinline__ void ldm_x4(uint32_t* r, uint32_t addr) {
    asm volatile("ldmatrix.sync.aligned.m8n8.x4.shared.b16 {%0,%1,%2,%3}, [%4];"
                 : "=r"(r[0]), "=r"(r[1]), "=r"(r[2]), "=r"(r[3]) : "r"(addr));
}
__device__ __forceinline__ void ldm_x4_t(uint32_t* r, uint32_t addr) {
    asm volatile("ldmatrix.sync.aligned.m8n8.x4.trans.shared.b16 {%0,%1,%2,%3}, [%4];"
                 : "=r"(r[0]), "=r"(r[1]), "=r"(r[2]), "=r"(r[3]) : "r"(addr));
}
__device__ __forceinline__ void mma16816(float* c, const uint32_t* a, uint32_t b0, uint32_t b1) {
    asm volatile(
        "mma.sync.aligned.m16n8k16.row.col.f32.f16.f16.f32 "
        "{%0,%1,%2,%3}, {%4,%5,%6,%7}, {%8,%9}, {%0,%1,%2,%3};"
        : "+f"(c[0]), "+f"(c[1]), "+f"(c[2]), "+f"(c[3])
        : "r"(a[0]), "r"(a[1]), "r"(a[2]), "r"(a[3]), "r"(b0), "r"(b1));
}

__global__ __launch_bounds__(128)
void nmt_gemm_mma(const float* __restrict__ bias) {
    extern __shared__ char sm[];
    __shared__ float rowsum[BM];
    const uint32_t sm_base = smem_u32(sm);
    const int tid = threadIdx.x;
    const int warp = tid >> 5, lane = tid & 31;
    const int warp_m = warp >> 1;        // 0..1 -> 64 rows
    const int warp_n = warp & 1;         // 0..1 -> 64 cols
    const int nt = blockIdx.x;
    const int mt = blockIdx.y;

    const __half* Ag = d_A2 + (size_t)mt * BM * HH;
    const __half* Bg = d_B2 + (size_t)nt * BN;

    const int a_row0 = tid >> 2;         // +32 steps
    const int a_q = tid & 3;
    const int b_row0 = tid >> 4;         // +8 steps
    const int b_q = tid & 15;

    if (tid < BM) rowsum[tid] = 0.f;

    float acc[4][8][4];
#pragma unroll
    for (int t = 0; t < 4; t++)
#pragma unroll
        for (int n = 0; n < 8; n++)
#pragma unroll
            for (int j = 0; j < 4; j++) acc[t][n][j] = 0.f;

    auto load_stage = [&](int s, int kb) {
        const uint32_t as = sm_base + s * STAGE_BYTES;
        const uint32_t bs = as + A_BYTES;
#pragma unroll
        for (int j = 0; j < 4; j++) {
            const int row = a_row0 + j * 32;
            cp16(as + row * 80 + a_q * 16,
                 Ag + (size_t)row * HH + kb * BK + a_q * 8);
        }
#pragma unroll
        for (int j = 0; j < 4; j++) {
            const int row = b_row0 + j * 8;
            cp16(bs + row * 272 + b_q * 16,
                 Bg + (size_t)(kb * BK + row) * VV + b_q * 8);
        }
    };

#pragma unroll
    for (int s = 0; s < STAGES - 1; s++) { load_stage(s, s); cp_commit(); }

    // per-warp ldmatrix base addresses (lane-dependent parts hoisted)
    const int a_lrow = warp_m * 64 + (lane & 15);
    const int b_lrow = (lane & 15);
    const int a_koff = (lane >> 4) * 16;
    const int b_noff = (warp_n * 64 + (lane >> 4) * 8) * 2;

    for (int it = 0; it < KTILES; it++) {
        cp_wait2();
        __syncthreads();
        if (it + STAGES - 1 < KTILES) load_stage((it + STAGES - 1) & (STAGES - 1), it + STAGES - 1);
        cp_commit();

        const uint32_t as = sm_base + (it & (STAGES - 1)) * STAGE_BYTES;
        const uint32_t bs = as + A_BYTES;

        // issue ALL fragment loads (both k2 halves) before the MMA bursts
        uint32_t af[2][4][4], bf[2][4][4];
#pragma unroll
        for (int k2 = 0; k2 < 2; k2++) {
#pragma unroll
            for (int t = 0; t < 4; t++)
                ldm_x4(af[k2][t], as + (a_lrow + t * 16) * 80 + k2 * 32 + a_koff);
#pragma unroll
            for (int p = 0; p < 4; p++)
                ldm_x4_t(bf[k2][p], bs + (k2 * 16 + b_lrow) * 272 + b_noff + p * 32);
        }
#pragma unroll
        for (int k2 = 0; k2 < 2; k2++)
#pragma unroll
            for (int t = 0; t < 4; t++)
#pragma unroll
                for (int n = 0; n < 8; n++)
                    mma16816(acc[t][n], af[k2][t],
                             bf[k2][n >> 1][(n & 1) * 2], bf[k2][n >> 1][(n & 1) * 2 + 1]);
    }

    // epilogue: add bias, store fp16 logits, fuse per-row sum(exp(logit))
    const int group = lane >> 2, tg = lane & 3;
#pragma unroll
    for (int t = 0; t < 4; t++) {
        const int lr0 = warp_m * 64 + t * 16 + group;
        const int lr1 = lr0 + 8;
        const int r0 = mt * BM + lr0;
        const int r1 = mt * BM + lr1;
        float s0 = 0.f, s1 = 0.f;
#pragma unroll
        for (int n = 0; n < 8; n++) {
            const int col = nt * BN + warp_n * 64 + n * 8 + tg * 2;
            const float2 bv = *(const float2*)(bias + col);
            const float v00 = acc[t][n][0] + bv.x, v01 = acc[t][n][1] + bv.y;
            const float v10 = acc[t][n][2] + bv.x, v11 = acc[t][n][3] + bv.y;
            if (r0 < MMROWS)
                *(__half2*)(d_logits + (size_t)r0 * VV + col) = __floats2half2_rn(v00, v01);
            if (r1 < MMROWS)
                *(__half2*)(d_logits + (size_t)r1 * VV + col) = __floats2half2_rn(v10, v11);
            s0 += __expf(v00) + __expf(v01);
            s1 += __expf(v10) + __expf(v11);
        }
        atomicAdd(&rowsum[lr0], s0);
        atomicAdd(&rowsum[lr1], s1);
    }
    __syncthreads();
    if (tid < BM) {
        const int r = mt * BM + tid;
        if (r < MMROWS) atomicAdd(&d_sumexp[r], rowsum[tid]);
    }
}

// ---------------- blend: half-vocab per CTA (64KB smem -> 3 CTAs/SM) ----------------
#define VHALF (VV / 2)
__global__ __launch_bounds__(512)
void nmt_blend_kernel(const float* __restrict__ weights,
                      const float* __restrict__ p_trans,
                      const float* __restrict__ trans_probs,
                      const float* __restrict__ probs,
                      const int* __restrict__ idxes,
                      float* __restrict__ out) {
    extern __shared__ float ts[];               // VHALF floats (64 KB)
    const int half = blockIdx.x;                // 0..1
    const int bt = blockIdx.y;                  // 0..799
    const int b = bt / TT;
    const int tid = threadIdx.x;
    const int vbase = half * VHALF;

    float4* tsv = (float4*)ts;
    const float4 z4 = make_float4(0.f, 0.f, 0.f, 0.f);
    for (int i = tid; i < VHALF / 4; i += 512) tsv[i] = z4;
    __syncthreads();

    const float* wrow = weights + (size_t)bt * SS;
    const float* pb   = probs + (size_t)b * SS * KK;
    const float* tpb  = trans_probs + (size_t)b * SS * KK;
    const int* ib     = idxes + (size_t)b * SS * KK;
    for (int i = tid; i < SS * KK; i += 512) {
        if (pb[i] > 0.05f) {
            const int v = ib[i] - vbase;
            if ((unsigned)v < (unsigned)VHALF)
                atomicAdd(&ts[v], tpb[i] * wrow[i >> 3]);
        }
    }
    __syncthreads();

    const float logZ = __logf(d_sumexp[bt]);
    const float pt = p_trans[bt];
    const float lom = __logf(1.f - pt) - logZ;

    // 8 halves per iter: uint4 load of fp16 logits, float4 ts reads, two float4 stores
    const uint4* lrow = (const uint4*)(d_logits + (size_t)bt * VV + vbase);
    float4* orow = (float4*)(out + (size_t)bt * VV + vbase);
    for (int i = tid; i < VHALF / 8; i += 512) {
        const uint4 lp = lrow[i];
        const __half2 h[4] = {
            *(const __half2*)&lp.x, *(const __half2*)&lp.y,
            *(const __half2*)&lp.z, *(const __half2*)&lp.w
        };
        float le[8];
#pragma unroll
        for (int j = 0; j < 4; j++) {
            const float2 f = __half22float2(h[j]);
            le[j * 2] = f.x; le[j * 2 + 1] = f.y;
        }
        const float4 t0 = tsv[i * 2];
        const float4 t1 = tsv[i * 2 + 1];
        const float te[8] = {t0.x, t0.y, t0.z, t0.w, t1.x, t1.y, t1.z, t1.w};
        float oe[8];
#pragma unroll
        for (int j = 0; j < 8; j++) {
            if (te[j] == 0.f) oe[j] = lom + le[j];
            else oe[j] = __logf(fmaf(pt, te[j], (1.f - pt) * __expf(le[j] - logZ)));
        }
        orow[i * 2]     = make_float4(oe[0], oe[1], oe[2], oe[3]);
        orow[i * 2 + 1] = make_float4(oe[4], oe[5], oe[6], oe[7]);
    }
}

// ---------------- launch ----------------
extern "C" void kernel_launch(void* const* d_in, const int* in_sizes, int n_in,
                              void* d_out, int out_size) {
    const float* dec_out     = (const float*)d_in[0];
    const float* W           = (const float*)d_in[1];
    const float* bias        = (const float*)d_in[2];
    const float* weights     = (const float*)d_in[3];
    const float* p_trans     = (const float*)d_in[4];
    const float* trans_probs = (const float*)d_in[5];
    const float* probs       = (const float*)d_in[6];
    const int*   idxes       = (const int*)d_in[7];
    float* out = (float*)d_out;

    zero_sumexp<<<(MMROWS + 255) / 256, 256>>>();
    conv_a_kernel<<<(MMROWS * 128 + 255) / 256, 256>>>(dec_out);
    conv_b_kernel<<<(HH * (VV / 4) + 255) / 256, 256>>>(W);

    cudaFuncSetAttribute(nmt_gemm_mma, cudaFuncAttributeMaxDynamicSharedMemorySize, GEMM_SMEM);
    nmt_gemm_mma<<<dim3(VV / BN, MPAD / BM), 128, GEMM_SMEM>>>(bias);

    const int blend_smem = VHALF * sizeof(float);    // 64000
    cudaFuncSetAttribute(nmt_blend_kernel, cudaFuncAttributeMaxDynamicSharedMemorySize, blend_smem);
    nmt_blend_kernel<<<dim3(2, MMROWS), 512, blend_smem>>>(weights, p_trans, trans_probs,
                                                           probs, idxes, out);
}

// round 12
// speedup vs baseline: 1.0143x; 1.0143x over previous
#include <cuda_runtime.h>
#include <cuda_fp16.h>
#include <cstdint>

// ---------------- problem constants ----------------
#define BB 8
#define TT 100
#define SS 400
#define KK 8
#define HH 512
#define VV 32000
#define MMROWS 800
#define MPAD 896

// fp16 operands (single GEMM, K=512)
__device__ __half d_A2[(size_t)MPAD * HH];        // 0.92 MB (pad rows stay zero-init)
__device__ __half d_B2[(size_t)HH * VV];          // 32.8 MB (fits in L2)
__device__ __half d_logits[(size_t)MMROWS * VV];  // 51.2 MB fp16 logits
__device__ float  d_sumexp[MMROWS];               // per-row sum of exp(logit)

// compacted scatter lists (per batch): entries with probs > 0.05
__device__ uint32_t d_cpack[BB * SS * KK];        // idx | (s << 15)
__device__ float    d_cval[BB * SS * KK];         // trans_probs value
__device__ int      d_ccount[BB];

static __device__ __forceinline__ uint32_t pack_h2(__half a, __half b) {
    return (uint32_t)__half_as_ushort(a) | ((uint32_t)__half_as_ushort(b) << 16);
}

__global__ __launch_bounds__(256)
void zero_accums() {
    const int i = blockIdx.x * 256 + threadIdx.x;
    if (i < MMROWS) d_sumexp[i] = 0.f;
    if (i < BB) d_ccount[i] = 0;
}

// ---------------- compaction: filter (b,s,k) entries once ----------------
__global__ __launch_bounds__(512)
void compact_kernel(const float* __restrict__ trans_probs,
                    const float* __restrict__ probs,
                    const int* __restrict__ idxes) {
    const int b = blockIdx.x;
    const int tid = threadIdx.x;
    const float* pb  = probs + (size_t)b * SS * KK;
    const float* tpb = trans_probs + (size_t)b * SS * KK;
    const int* ib    = idxes + (size_t)b * SS * KK;
    for (int i = tid; i < SS * KK; i += 512) {
        if (pb[i] > 0.05f) {
            const int j = atomicAdd(&d_ccount[b], 1);
            d_cpack[b * SS * KK + j] = (uint32_t)ib[i] | ((uint32_t)(i >> 3) << 15);
            d_cval[b * SS * KK + j]  = tpb[i];
        }
    }
}

// ---------------- conversion: A -> fp16 ----------------
__global__ __launch_bounds__(256)
void conv_a_kernel(const float* __restrict__ A) {
    const int idx = blockIdx.x * 256 + threadIdx.x;      // 800*128
    if (idx >= MMROWS * 128) return;
    const int row = idx >> 7;
    const int kq = idx & 127;
    const float4 v = *(const float4*)(A + (size_t)row * HH + kq * 4);
    uint2 p;
    p.x = pack_h2(__float2half_rn(v.x), __float2half_rn(v.y));
    p.y = pack_h2(__float2half_rn(v.z), __float2half_rn(v.w));
    *(uint2*)(d_A2 + (size_t)row * HH + kq * 4) = p;
}

// ---------------- conversion: W -> fp16 ----------------
__global__ __launch_bounds__(256)
void conv_b_kernel(const float* __restrict__ W) {
    const int idx = blockIdx.x * 256 + threadIdx.x;      // 512*8000
    if (idx >= HH * (VV / 4)) return;
    const float4 v = *(const float4*)(W + (size_t)idx * 4);
    uint2 p;
    p.x = pack_h2(__float2half_rn(v.x), __float2half_rn(v.y));
    p.y = pack_h2(__float2half_rn(v.z), __float2half_rn(v.w));
    *(uint2*)(d_B2 + (size_t)idx * 4) = p;
}

// ---------------- mma.sync GEMM + fused row-sumexp (R10 form) ----------------
// CTA 128x128, 128 threads = 4 warps (2x2), warp tile 64x64, 4-stage pipeline.
#define BM 128
#define BN 128
#define BK 32
#define STAGES 4
#define KTILES (HH / BK)             // 16
#define A_STRIDE 40                  // halves/row (32 + 8 pad) -> 80 B
#define B_STRIDE 136                 // halves/row (128 + 8 pad) -> 272 B
#define A_BYTES (BM * A_STRIDE * 2)  // 10240
#define B_BYTES (BK * B_STRIDE * 2)  // 8704
#define STAGE_BYTES (A_BYTES + B_BYTES)  // 18944
#define GEMM_SMEM (STAGES * STAGE_BYTES) // 75776

__device__ __forceinline__ uint32_t smem_u32(const void* p) {
    uint32_t a;
    asm("{ .reg .u64 t; cvta.to.shared.u64 t, %1; cvt.u32.u64 %0, t; }" : "=r"(a) : "l"(p));
    return a;
}
__device__ __forceinline__ void cp16(uint32_t dst, const void* src) {
    asm volatile("cp.async.cg.shared.global [%0], [%1], 16;" :: "r"(dst), "l"(src) : "memory");
}
__device__ __forceinline__ void cp_commit() {
    asm volatile("cp.async.commit_group;" ::: "memory");
}
__device__ __forceinline__ void cp_wait2() {
    asm volatile("cp.async.wait_group 2;" ::: "memory");
}
__device__ __forceinline__ void ldm_x4(uint32_t* r, uint32_t addr) {
    asm volatile("ldmatrix.sync.aligned.m8n8.x4.shared.b16 {%0,%1,%2,%3}, [%4];"
                 : "=r"(r[0]), "=r"(r[1]), "=r"(r[2]), "=r"(r[3]) : "r"(addr));
}
__device__ __forceinline__ void ldm_x4_t(uint32_t* r, uint32_t addr) {
    asm volatile("ldmatrix.sync.aligned.m8n8.x4.trans.shared.b16 {%0,%1,%2,%3}, [%4];"
                 : "=r"(r[0]), "=r"(r[1]), "=r"(r[2]), "=r"(r[3]) : "r"(addr));
}
__device__ __forceinline__ void mma16816(float* c, const uint32_t* a, uint32_t b0, uint32_t b1) {
    asm volatile(
        "mma.sync.aligned.m16n8k16.row.col.f32.f16.f16.f32 "
        "{%0,%1,%2,%3}, {%4,%5,%6,%7}, {%8,%9}, {%0,%1,%2,%3};"
        : "+f"(c[0]), "+f"(c[1]), "+f"(c[2]), "+f"(c[3])
        : "r"(a[0]), "r"(a[1]), "r"(a[2]), "r"(a[3]), "r"(b0), "r"(b1));
}

__global__ __launch_bounds__(128)
void nmt_gemm_mma(const float* __restrict__ bias) {
    extern __shared__ char sm[];
    __shared__ float rowsum[BM];
    const uint32_t sm_base = smem_u32(sm);
    const int tid = threadIdx.x;
    const int warp = tid >> 5, lane = tid & 31;
    const int warp_m = warp >> 1;        // 0..1 -> 64 rows
    const int warp_n = warp & 1;         // 0..1 -> 64 cols
    const int nt = blockIdx.x;
    const int mt = blockIdx.y;

    const __half* Ag = d_A2 + (size_t)mt * BM * HH;
    const __half* Bg = d_B2 + (size_t)nt * BN;

    const int a_row0 = tid >> 2;         // +32 steps
    const int a_q = tid & 3;
    const int b_row0 = tid >> 4;         // +8 steps
    const int b_q = tid & 15;

    if (tid < BM) rowsum[tid] = 0.f;

    float acc[4][8][4];
#pragma unroll
    for (int t = 0; t < 4; t++)
#pragma unroll
        for (int n = 0; n < 8; n++)
#pragma unroll
            for (int j = 0; j < 4; j++) acc[t][n][j] = 0.f;

    auto load_stage = [&](int s, int kb) {
        const uint32_t as = sm_base + s * STAGE_BYTES;
        const uint32_t bs = as + A_BYTES;
#pragma unroll
        for (int j = 0; j < 4; j++) {
            const int row = a_row0 + j * 32;
            cp16(as + row * 80 + a_q * 16,
                 Ag + (size_t)row * HH + kb * BK + a_q * 8);
        }
#pragma unroll
        for (int j = 0; j < 4; j++) {
            const int row = b_row0 + j * 8;
            cp16(bs + row * 272 + b_q * 16,
                 Bg + (size_t)(kb * BK + row) * VV + b_q * 8);
        }
    };

#pragma unroll
    for (int s = 0; s < STAGES - 1; s++) { load_stage(s, s); cp_commit(); }

    for (int it = 0; it < KTILES; it++) {
        cp_wait2();
        __syncthreads();
        if (it + STAGES - 1 < KTILES) load_stage((it + STAGES - 1) & (STAGES - 1), it + STAGES - 1);
        cp_commit();

        const uint32_t as = sm_base + (it & (STAGES - 1)) * STAGE_BYTES;
        const uint32_t bs = as + A_BYTES;
#pragma unroll
        for (int k2 = 0; k2 < 2; k2++) {
            uint32_t af[4][4];
#pragma unroll
            for (int t = 0; t < 4; t++)
                ldm_x4(af[t], as + (warp_m * 64 + t * 16 + (lane & 15)) * 80
                              + k2 * 32 + (lane >> 4) * 16);
            uint32_t bf[4][4];
#pragma unroll
            for (int p = 0; p < 4; p++)
                ldm_x4_t(bf[p], bs + (k2 * 16 + (lane & 15)) * 272
                               + (warp_n * 64 + p * 16 + (lane >> 4) * 8) * 2);
#pragma unroll
            for (int t = 0; t < 4; t++)
#pragma unroll
                for (int n = 0; n < 8; n++)
                    mma16816(acc[t][n], af[t], bf[n >> 1][(n & 1) * 2], bf[n >> 1][(n & 1) * 2 + 1]);
        }
    }

    // epilogue: add bias, store fp16 logits, fuse per-row sum(exp(logit))
    const int group = lane >> 2, tg = lane & 3;
#pragma unroll
    for (int t = 0; t < 4; t++) {
        const int lr0 = warp_m * 64 + t * 16 + group;
        const int lr1 = lr0 + 8;
        const int r0 = mt * BM + lr0;
        const int r1 = mt * BM + lr1;
        float s0 = 0.f, s1 = 0.f;
#pragma unroll
        for (int n = 0; n < 8; n++) {
            const int col = nt * BN + warp_n * 64 + n * 8 + tg * 2;
            const float2 bv = *(const float2*)(bias + col);
            const float v00 = acc[t][n][0] + bv.x, v01 = acc[t][n][1] + bv.y;
            const float v10 = acc[t][n][2] + bv.x, v11 = acc[t][n][3] + bv.y;
            if (r0 < MMROWS)
                *(__half2*)(d_logits + (size_t)r0 * VV + col) = __floats2half2_rn(v00, v01);
            if (r1 < MMROWS)
                *(__half2*)(d_logits + (size_t)r1 * VV + col) = __floats2half2_rn(v10, v11);
            s0 += __expf(v00) + __expf(v01);
            s1 += __expf(v10) + __expf(v11);
        }
        atomicAdd(&rowsum[lr0], s0);
        atomicAdd(&rowsum[lr1], s1);
    }
    __syncthreads();
    if (tid < BM) {
        const int r = mt * BM + tid;
        if (r < MMROWS) atomicAdd(&d_sumexp[r], rowsum[tid]);
    }
}

// ---------------- blend: half-vocab per CTA, compacted scatter ----------------
#define VHALF (VV / 2)
__global__ __launch_bounds__(512)
void nmt_blend_kernel(const float* __restrict__ weights,
                      const float* __restrict__ p_trans,
                      float* __restrict__ out) {
    extern __shared__ float ts[];               // VHALF floats (64 KB)
    const int half = blockIdx.x;                // 0..1
    const int bt = blockIdx.y;                  // 0..799
    const int b = bt / TT;
    const int tid = threadIdx.x;
    const int vbase = half * VHALF;

    float4* tsv = (float4*)ts;
    const float4 z4 = make_float4(0.f, 0.f, 0.f, 0.f);
    for (int i = tid; i < VHALF / 4; i += 512) tsv[i] = z4;
    __syncthreads();

    // scatter from compacted list
    const float* wrow = weights + (size_t)bt * SS;
    const int cnt = d_ccount[b];
    const uint32_t* cp = d_cpack + b * SS * KK;
    const float* cv = d_cval + b * SS * KK;
    for (int j = tid; j < cnt; j += 512) {
        const uint32_t u = cp[j];
        const int v = (int)(u & 0x7FFFu) - vbase;
        if ((unsigned)v < (unsigned)VHALF)
            atomicAdd(&ts[v], cv[j] * wrow[u >> 15]);
    }
    __syncthreads();

    const float logZ = __logf(d_sumexp[bt]);
    const float pt = p_trans[bt];
    const float lom = __logf(1.f - pt) - logZ;

    // 8 halves per iter: uint4 load of fp16 logits, float4 ts reads, two float4 stores
    const uint4* lrow = (const uint4*)(d_logits + (size_t)bt * VV + vbase);
    float4* orow = (float4*)(out + (size_t)bt * VV + vbase);
    for (int i = tid; i < VHALF / 8; i += 512) {
        const uint4 lp = lrow[i];
        const __half2 h[4] = {
            *(const __half2*)&lp.x, *(const __half2*)&lp.y,
            *(const __half2*)&lp.z, *(const __half2*)&lp.w
        };
        float le[8];
#pragma unroll
        for (int j = 0; j < 4; j++) {
            const float2 f = __half22float2(h[j]);
            le[j * 2] = f.x; le[j * 2 + 1] = f.y;
        }
        const float4 t0 = tsv[i * 2];
        const float4 t1 = tsv[i * 2 + 1];
        const float te[8] = {t0.x, t0.y, t0.z, t0.w, t1.x, t1.y, t1.z, t1.w};
        float oe[8];
#pragma unroll
        for (int j = 0; j < 8; j++) {
            if (te[j] == 0.f) oe[j] = lom + le[j];
            else oe[j] = __logf(fmaf(pt, te[j], (1.f - pt) * __expf(le[j] - logZ)));
        }
        orow[i * 2]     = make_float4(oe[0], oe[1], oe[2], oe[3]);
        orow[i * 2 + 1] = make_float4(oe[4], oe[5], oe[6], oe[7]);
    }
}

// ---------------- launch ----------------
extern "C" void kernel_launch(void* const* d_in, const int* in_sizes, int n_in,
                              void* d_out, int out_size) {
    const float* dec_out     = (const float*)d_in[0];
    const float* W           = (const float*)d_in[1];
    const float* bias        = (const float*)d_in[2];
    const float* weights     = (const float*)d_in[3];
    const float* p_trans     = (const float*)d_in[4];
    const float* trans_probs = (const float*)d_in[5];
    const float* probs       = (const float*)d_in[6];
    const int*   idxes       = (const int*)d_in[7];
    float* out = (float*)d_out;

    zero_accums<<<(MMROWS + 255) / 256, 256>>>();
    compact_kernel<<<BB, 512>>>(trans_probs, probs, idxes);
    conv_a_kernel<<<(MMROWS * 128 + 255) / 256, 256>>>(dec_out);
    conv_b_kernel<<<(HH * (VV / 4) + 255) / 256, 256>>>(W);

    cudaFuncSetAttribute(nmt_gemm_mma, cudaFuncAttributeMaxDynamicSharedMemorySize, GEMM_SMEM);
    nmt_gemm_mma<<<dim3(VV / BN, MPAD / BM), 128, GEMM_SMEM>>>(bias);

    const int blend_smem = VHALF * sizeof(float);    // 64000
    cudaFuncSetAttribute(nmt_blend_kernel, cudaFuncAttributeMaxDynamicSharedMemorySize, blend_smem);
    nmt_blend_kernel<<<dim3(2, MMROWS), 512, blend_smem>>>(weights, p_trans, out);
}

// round 13
// speedup vs baseline: 1.0818x; 1.0666x over previous
#include <cuda_runtime.h>
#include <cuda_fp16.h>
#include <cstdint>

// ---------------- problem constants ----------------
#define BB 8
#define TT 100
#define SS 400
#define KK 8
#define HH 512
#define VV 32000
#define MMROWS 800
#define MPAD 896
#define VQ 8000                 // vocab quarter
#define NQ 4

// fp16 operands (single GEMM, K=512)
__device__ __half d_A2[(size_t)MPAD * HH];        // 0.92 MB (pad rows stay zero-init)
__device__ __half d_B2[(size_t)HH * VV];          // 32.8 MB (fits in L2)
__device__ __half d_logits[(size_t)MMROWS * VV];  // 51.2 MB fp16 logits
__device__ float  d_sumexp[MMROWS];               // per-row sum of exp(logit)

// bucketed compacted scatter lists: [batch][vocab-quarter]
__device__ uint32_t d_cpack[BB * NQ * SS * KK];   // localv | (s << 13)
__device__ float    d_cval[BB * NQ * SS * KK];    // trans_probs value
__device__ int      d_ccount[BB * NQ];

static __device__ __forceinline__ uint32_t pack_h2(__half a, __half b) {
    return (uint32_t)__half_as_ushort(a) | ((uint32_t)__half_as_ushort(b) << 16);
}

__global__ __launch_bounds__(256)
void zero_accums() {
    const int i = blockIdx.x * 256 + threadIdx.x;
    if (i < MMROWS) d_sumexp[i] = 0.f;
    if (i < BB * NQ) d_ccount[i] = 0;
}

// ---------------- compaction: filter + bucket by vocab quarter ----------------
__global__ __launch_bounds__(512)
void compact_kernel(const float* __restrict__ trans_probs,
                    const float* __restrict__ probs,
                    const int* __restrict__ idxes) {
    const int b = blockIdx.x;
    const int tid = threadIdx.x;
    const float* pb  = probs + (size_t)b * SS * KK;
    const float* tpb = trans_probs + (size_t)b * SS * KK;
    const int* ib    = idxes + (size_t)b * SS * KK;
    for (int i = tid; i < SS * KK; i += 512) {
        if (pb[i] > 0.05f) {
            const int idx = ib[i];
            const int q = idx / VQ;                       // 0..3
            const int bq = b * NQ + q;
            const int j = atomicAdd(&d_ccount[bq], 1);
            d_cpack[(size_t)bq * SS * KK + j] = (uint32_t)(idx - q * VQ) | ((uint32_t)(i >> 3) << 13);
            d_cval[(size_t)bq * SS * KK + j]  = tpb[i];
        }
    }
}

// ---------------- conversion: A -> fp16 ----------------
__global__ __launch_bounds__(256)
void conv_a_kernel(const float* __restrict__ A) {
    const int idx = blockIdx.x * 256 + threadIdx.x;      // 800*128
    if (idx >= MMROWS * 128) return;
    const int row = idx >> 7;
    const int kq = idx & 127;
    const float4 v = *(const float4*)(A + (size_t)row * HH + kq * 4);
    uint2 p;
    p.x = pack_h2(__float2half_rn(v.x), __float2half_rn(v.y));
    p.y = pack_h2(__float2half_rn(v.z), __float2half_rn(v.w));
    *(uint2*)(d_A2 + (size_t)row * HH + kq * 4) = p;
}

// ---------------- conversion: W -> fp16 (streaming reads) ----------------
__global__ __launch_bounds__(256)
void conv_b_kernel(const float* __restrict__ W) {
    const int idx = blockIdx.x * 256 + threadIdx.x;      // 512*8000
    if (idx >= HH * (VV / 4)) return;
    const float4 v = __ldcs((const float4*)(W + (size_t)idx * 4));
    uint2 p;
    p.x = pack_h2(__float2half_rn(v.x), __float2half_rn(v.y));
    p.y = pack_h2(__float2half_rn(v.z), __float2half_rn(v.w));
    *(uint2*)(d_B2 + (size_t)idx * 4) = p;
}

// ---------------- mma.sync GEMM + fused row-sumexp (R12 form, unchanged) ----------------
#define BM 128
#define BN 128
#define BK 32
#define STAGES 4
#define KTILES (HH / BK)             // 16
#define A_STRIDE 40
#define B_STRIDE 136
#define A_BYTES (BM * A_STRIDE * 2)  // 10240
#define B_BYTES (BK * B_STRIDE * 2)  // 8704
#define STAGE_BYTES (A_BYTES + B_BYTES)  // 18944
#define GEMM_SMEM (STAGES * STAGE_BYTES) // 75776

__device__ __forceinline__ uint32_t smem_u32(const void* p) {
    uint32_t a;
    asm("{ .reg .u64 t; cvta.to.shared.u64 t, %1; cvt.u32.u64 %0, t; }" : "=r"(a) : "l"(p));
    return a;
}
__device__ __forceinline__ void cp16(uint32_t dst, const void* src) {
    asm volatile("cp.async.cg.shared.global [%0], [%1], 16;" :: "r"(dst), "l"(src) : "memory");
}
__device__ __forceinline__ void cp_commit() {
    asm volatile("cp.async.commit_group;" ::: "memory");
}
__device__ __forceinline__ void cp_wait2() {
    asm volatile("cp.async.wait_group 2;" ::: "memory");
}
__device__ __forceinline__ void ldm_x4(uint32_t* r, uint32_t addr) {
    asm volatile("ldmatrix.sync.aligned.m8n8.x4.shared.b16 {%0,%1,%2,%3}, [%4];"
                 : "=r"(r[0]), "=r"(r[1]), "=r"(r[2]), "=r"(r[3]) : "r"(addr));
}
__device__ __forceinline__ void ldm_x4_t(uint32_t* r, uint32_t addr) {
    asm volatile("ldmatrix.sync.aligned.m8n8.x4.trans.shared.b16 {%0,%1,%2,%3}, [%4];"
                 : "=r"(r[0]), "=r"(r[1]), "=r"(r[2]), "=r"(r[3]) : "r"(addr));
}
__device__ __forceinline__ void mma16816(float* c, const uint32_t* a, uint32_t b0, uint32_t b1) {
    asm volatile(
        "mma.sync.aligned.m16n8k16.row.col.f32.f16.f16.f32 "
        "{%0,%1,%2,%3}, {%4,%5,%6,%7}, {%8,%9}, {%0,%1,%2,%3};"
        : "+f"(c[0]), "+f"(c[1]), "+f"(c[2]), "+f"(c[3])
        : "r"(a[0]), "r"(a[1]), "r"(a[2]), "r"(a[3]), "r"(b0), "r"(b1));
}

__global__ __launch_bounds__(128)
void nmt_gemm_mma(const float* __restrict__ bias) {
    extern __shared__ char sm[];
    __shared__ float rowsum[BM];
    const uint32_t sm_base = smem_u32(sm);
    const int tid = threadIdx.x;
    const int warp = tid >> 5, lane = tid & 31;
    const int warp_m = warp >> 1;
    const int warp_n = warp & 1;
    const int nt = blockIdx.x;
    const int mt = blockIdx.y;

    const __half* Ag = d_A2 + (size_t)mt * BM * HH;
    const __half* Bg = d_B2 + (size_t)nt * BN;

    const int a_row0 = tid >> 2;
    const int a_q = tid & 3;
    const int b_row0 = tid >> 4;
    const int b_q = tid & 15;

    if (tid < BM) rowsum[tid] = 0.f;

    float acc[4][8][4];
#pragma unroll
    for (int t = 0; t < 4; t++)
#pragma unroll
        for (int n = 0; n < 8; n++)
#pragma unroll
            for (int j = 0; j < 4; j++) acc[t][n][j] = 0.f;

    auto load_stage = [&](int s, int kb) {
        const uint32_t as = sm_base + s * STAGE_BYTES;
        const uint32_t bs = as + A_BYTES;
#pragma unroll
        for (int j = 0; j < 4; j++) {
            const int row = a_row0 + j * 32;
            cp16(as + row * 80 + a_q * 16,
                 Ag + (size_t)row * HH + kb * BK + a_q * 8);
        }
#pragma unroll
        for (int j = 0; j < 4; j++) {
            const int row = b_row0 + j * 8;
            cp16(bs + row * 272 + b_q * 16,
                 Bg + (size_t)(kb * BK + row) * VV + b_q * 8);
        }
    };

#pragma unroll
    for (int s = 0; s < STAGES - 1; s++) { load_stage(s, s); cp_commit(); }

    for (int it = 0; it < KTILES; it++) {
        cp_wait2();
        __syncthreads();
        if (it + STAGES - 1 < KTILES) load_stage((it + STAGES - 1) & (STAGES - 1), it + STAGES - 1);
        cp_commit();

        const uint32_t as = sm_base + (it & (STAGES - 1)) * STAGE_BYTES;
        const uint32_t bs = as + A_BYTES;
#pragma unroll
        for (int k2 = 0; k2 < 2; k2++) {
            uint32_t af[4][4];
#pragma unroll
            for (int t = 0; t < 4; t++)
                ldm_x4(af[t], as + (warp_m * 64 + t * 16 + (lane & 15)) * 80
                              + k2 * 32 + (lane >> 4) * 16);
            uint32_t bf[4][4];
#pragma unroll
            for (int p = 0; p < 4; p++)
                ldm_x4_t(bf[p], bs + (k2 * 16 + (lane & 15)) * 272
                               + (warp_n * 64 + p * 16 + (lane >> 4) * 8) * 2);
#pragma unroll
            for (int t = 0; t < 4; t++)
#pragma unroll
                for (int n = 0; n < 8; n++)
                    mma16816(acc[t][n], af[t], bf[n >> 1][(n & 1) * 2], bf[n >> 1][(n & 1) * 2 + 1]);
        }
    }

    const int group = lane >> 2, tg = lane & 3;
#pragma unroll
    for (int t = 0; t < 4; t++) {
        const int lr0 = warp_m * 64 + t * 16 + group;
        const int lr1 = lr0 + 8;
        const int r0 = mt * BM + lr0;
        const int r1 = mt * BM + lr1;
        float s0 = 0.f, s1 = 0.f;
#pragma unroll
        for (int n = 0; n < 8; n++) {
            const int col = nt * BN + warp_n * 64 + n * 8 + tg * 2;
            const float2 bv = *(const float2*)(bias + col);
            const float v00 = acc[t][n][0] + bv.x, v01 = acc[t][n][1] + bv.y;
            const float v10 = acc[t][n][2] + bv.x, v11 = acc[t][n][3] + bv.y;
            if (r0 < MMROWS)
                *(__half2*)(d_logits + (size_t)r0 * VV + col) = __floats2half2_rn(v00, v01);
            if (r1 < MMROWS)
                *(__half2*)(d_logits + (size_t)r1 * VV + col) = __floats2half2_rn(v10, v11);
            s0 += __expf(v00) + __expf(v01);
            s1 += __expf(v10) + __expf(v11);
        }
        atomicAdd(&rowsum[lr0], s0);
        atomicAdd(&rowsum[lr1], s1);
    }
    __syncthreads();
    if (tid < BM) {
        const int r = mt * BM + tid;
        if (r < MMROWS) atomicAdd(&d_sumexp[r], rowsum[tid]);
    }
}

// ---------------- blend: quarter-vocab per CTA, bucketed scatter ----------------
__global__ __launch_bounds__(512)
void nmt_blend_kernel(const float* __restrict__ weights,
                      const float* __restrict__ p_trans,
                      float* __restrict__ out) {
    extern __shared__ float ts[];               // VQ floats (32 KB)
    const int q = blockIdx.x;                   // 0..3
    const int bt = blockIdx.y;                  // 0..799
    const int b = bt / TT;
    const int tid = threadIdx.x;
    const int vbase = q * VQ;

    float4* tsv = (float4*)ts;
    const float4 z4 = make_float4(0.f, 0.f, 0.f, 0.f);
    for (int i = tid; i < VQ / 4; i += 512) tsv[i] = z4;
    __syncthreads();

    // scatter from this quarter's bucket (all entries hit; no bounds filter)
    const float* wrow = weights + (size_t)bt * SS;
    const int bq = b * NQ + q;
    const int cnt = d_ccount[bq];
    const uint32_t* cp = d_cpack + (size_t)bq * SS * KK;
    const float* cv = d_cval + (size_t)bq * SS * KK;
    for (int j = tid; j < cnt; j += 512) {
        const uint32_t u = cp[j];
        atomicAdd(&ts[u & 0x1FFFu], cv[j] * wrow[u >> 13]);
    }
    __syncthreads();

    const float logZ = __logf(d_sumexp[bt]);
    const float pt = p_trans[bt];
    const float lom = __logf(1.f - pt) - logZ;

    // 8 halves per iter: uint4 load of fp16 logits, float4 ts reads, two float4 stores
    const uint4* lrow = (const uint4*)(d_logits + (size_t)bt * VV + vbase);
    float4* orow = (float4*)(out + (size_t)bt * VV + vbase);
    for (int i = tid; i < VQ / 8; i += 512) {
        const uint4 lp = lrow[i];
        const __half2 h[4] = {
            *(const __half2*)&lp.x, *(const __half2*)&lp.y,
            *(const __half2*)&lp.z, *(const __half2*)&lp.w
        };
        float le[8];
#pragma unroll
        for (int j = 0; j < 4; j++) {
            const float2 f = __half22float2(h[j]);
            le[j * 2] = f.x; le[j * 2 + 1] = f.y;
        }
        const float4 t0 = tsv[i * 2];
        const float4 t1 = tsv[i * 2 + 1];
        const float te[8] = {t0.x, t0.y, t0.z, t0.w, t1.x, t1.y, t1.z, t1.w};
        float oe[8];
#pragma unroll
        for (int j = 0; j < 8; j++) {
            if (te[j] == 0.f) oe[j] = lom + le[j];
            else oe[j] = __logf(fmaf(pt, te[j], __expf(le[j] + lom)));
        }
        orow[i * 2]     = make_float4(oe[0], oe[1], oe[2], oe[3]);
        orow[i * 2 + 1] = make_float4(oe[4], oe[5], oe[6], oe[7]);
    }
}

// ---------------- launch ----------------
extern "C" void kernel_launch(void* const* d_in, const int* in_sizes, int n_in,
                              void* d_out, int out_size) {
    const float* dec_out     = (const float*)d_in[0];
    const float* W           = (const float*)d_in[1];
    const float* bias        = (const float*)d_in[2];
    const float* weights     = (const float*)d_in[3];
    const float* p_trans     = (const float*)d_in[4];
    const float* trans_probs = (const float*)d_in[5];
    const float* probs       = (const float*)d_in[6];
    const int*   idxes       = (const int*)d_in[7];
    float* out = (float*)d_out;

    zero_accums<<<(MMROWS + 255) / 256, 256>>>();
    compact_kernel<<<BB, 512>>>(trans_probs, probs, idxes);
    conv_a_kernel<<<(MMROWS * 128 + 255) / 256, 256>>>(dec_out);
    conv_b_kernel<<<(HH * (VV / 4) + 255) / 256, 256>>>(W);

    cudaFuncSetAttribute(nmt_gemm_mma, cudaFuncAttributeMaxDynamicSharedMemorySize, GEMM_SMEM);
    nmt_gemm_mma<<<dim3(VV / BN, MPAD / BM), 128, GEMM_SMEM>>>(bias);

    const int blend_smem = VQ * sizeof(float);       // 32000
    cudaFuncSetAttribute(nmt_blend_kernel, cudaFuncAttributeMaxDynamicSharedMemorySize, blend_smem);
    nmt_blend_kernel<<<dim3(NQ, MMROWS), 512, blend_smem>>>(weights, p_trans, out);
}

// round 15
// speedup vs baseline: 1.0963x; 1.0134x over previous
#include <cuda_runtime.h>
#include <cuda_fp16.h>
#include <cstdint>

// ---------------- problem constants ----------------
#define BB 8
#define TT 100
#define SS 400
#define KK 8
#define HH 512
#define VV 32000
#define MMROWS 800
#define MPAD 896
#define VQ 4000                 // vocab eighth
#define NQ 8

// fp16 operands (single GEMM, K=512)
__device__ __half d_A2[(size_t)MPAD * HH];        // 0.92 MB (pad rows stay zero-init)
__device__ __half d_B2[(size_t)HH * VV];          // 32.8 MB (fits in L2)
__device__ __half d_logits[(size_t)MMROWS * VV];  // 51.2 MB fp16 logits
__device__ float  d_sumexp[MMROWS];               // per-row sum of exp(logit)

// bucketed compacted scatter lists: [batch][vocab-eighth]
__device__ uint32_t d_cpack[BB * NQ * SS * KK];   // localv | (s << 12)
__device__ float    d_cval[BB * NQ * SS * KK];    // trans_probs value
__device__ int      d_ccount[BB * NQ];

static __device__ __forceinline__ uint32_t pack_h2(__half a, __half b) {
    return (uint32_t)__half_as_ushort(a) | ((uint32_t)__half_as_ushort(b) << 16);
}

__global__ __launch_bounds__(256)
void zero_accums() {
    const int i = blockIdx.x * 256 + threadIdx.x;
    if (i < MMROWS) d_sumexp[i] = 0.f;
    if (i < BB * NQ) d_ccount[i] = 0;
}

// ---------------- compaction: filter + bucket by vocab eighth ----------------
__global__ __launch_bounds__(512)
void compact_kernel(const float* __restrict__ trans_probs,
                    const float* __restrict__ probs,
                    const int* __restrict__ idxes) {
    const int b = blockIdx.x;
    const int tid = threadIdx.x;
    const float* pb  = probs + (size_t)b * SS * KK;
    const float* tpb = trans_probs + (size_t)b * SS * KK;
    const int* ib    = idxes + (size_t)b * SS * KK;
    for (int i = tid; i < SS * KK; i += 512) {
        if (pb[i] > 0.05f) {
            const int idx = ib[i];
            const int q = idx / VQ;                       // 0..7
            const int bq = b * NQ + q;
            const int j = atomicAdd(&d_ccount[bq], 1);
            d_cpack[(size_t)bq * SS * KK + j] = (uint32_t)(idx - q * VQ) | ((uint32_t)(i >> 3) << 12);
            d_cval[(size_t)bq * SS * KK + j]  = tpb[i];
        }
    }
}

// ---------------- conversion: A -> fp16 ----------------
__global__ __launch_bounds__(256)
void conv_a_kernel(const float* __restrict__ A) {
    const int idx = blockIdx.x * 256 + threadIdx.x;      // 800*128
    if (idx >= MMROWS * 128) return;
    const int row = idx >> 7;
    const int kq = idx & 127;
    const float4 v = *(const float4*)(A + (size_t)row * HH + kq * 4);
    uint2 p;
    p.x = pack_h2(__float2half_rn(v.x), __float2half_rn(v.y));
    p.y = pack_h2(__float2half_rn(v.z), __float2half_rn(v.w));
    *(uint2*)(d_A2 + (size_t)row * HH + kq * 4) = p;
}

// ---------------- conversion: W -> fp16 (4 independent float4 per thread) ----------------
#define CB_TOT (HH * VV / 4)    // 4.096M float4 slots
__global__ __launch_bounds__(256)
void conv_b_kernel(const float* __restrict__ W) {
    const int t = blockIdx.x * 256 + threadIdx.x;        // 1.024M threads
    const int n_thr = CB_TOT / 4;                         // 1.024M
    if (t >= n_thr) return;
    float4 v[4];
#pragma unroll
    for (int j = 0; j < 4; j++)
        v[j] = __ldcs((const float4*)(W + (size_t)(t + j * n_thr) * 4));
#pragma unroll
    for (int j = 0; j < 4; j++) {
        uint2 p;
        p.x = pack_h2(__float2half_rn(v[j].x), __float2half_rn(v[j].y));
        p.y = pack_h2(__float2half_rn(v[j].z), __float2half_rn(v[j].w));
        *(uint2*)(d_B2 + (size_t)(t + j * n_thr) * 4) = p;
    }
}

// ---------------- mma.sync GEMM + fused row-sumexp (unchanged) ----------------
#define BM 128
#define BN 128
#define BK 32
#define STAGES 4
#define KTILES (HH / BK)             // 16
#define A_STRIDE 40
#define B_STRIDE 136
#define A_BYTES (BM * A_STRIDE * 2)  // 10240
#define B_BYTES (BK * B_STRIDE * 2)  // 8704
#define STAGE_BYTES (A_BYTES + B_BYTES)  // 18944
#define GEMM_SMEM (STAGES * STAGE_BYTES) // 75776

__device__ __forceinline__ uint32_t smem_u32(const void* p) {
    uint32_t a;
    asm("{ .reg .u64 t; cvta.to.shared.u64 t, %1; cvt.u32.u64 %0, t; }" : "=r"(a) : "l"(p));
    return a;
}
__device__ __forceinline__ void cp16(uint32_t dst, const void* src) {
    asm volatile("cp.async.cg.shared.global [%0], [%1], 16;" :: "r"(dst), "l"(src) : "memory");
}
__device__ __forceinline__ void cp_commit() {
    asm volatile("cp.async.commit_group;" ::: "memory");
}
__device__ __forceinline__ void cp_wait2() {
    asm volatile("cp.async.wait_group 2;" ::: "memory");
}
__device__ __forceinline__ void ldm_x4(uint32_t* r, uint32_t addr) {
    asm volatile("ldmatrix.sync.aligned.m8n8.x4.shared.b16 {%0,%1,%2,%3}, [%4];"
                 : "=r"(r[0]), "=r"(r[1]), "=r"(r[2]), "=r"(r[3]) : "r"(addr));
}
__device__ __forceinline__ void ldm_x4_t(uint32_t* r, uint32_t addr) {
    asm volatile("ldmatrix.sync.aligned.m8n8.x4.trans.shared.b16 {%0,%1,%2,%3}, [%4];"
                 : "=r"(r[0]), "=r"(r[1]), "=r"(r[2]), "=r"(r[3]) : "r"(addr));
}
__device__ __forceinline__ void mma16816(float* c, const uint32_t* a, uint32_t b0, uint32_t b1) {
    asm volatile(
        "mma.sync.aligned.m16n8k16.row.col.f32.f16.f16.f32 "
        "{%0,%1,%2,%3}, {%4,%5,%6,%7}, {%8,%9}, {%0,%1,%2,%3};"
        : "+f"(c[0]), "+f"(c[1]), "+f"(c[2]), "+f"(c[3])
        : "r"(a[0]), "r"(a[1]), "r"(a[2]), "r"(a[3]), "r"(b0), "r"(b1));
}

__global__ __launch_bounds__(128)
void nmt_gemm_mma(const float* __restrict__ bias) {
    extern __shared__ char sm[];
    __shared__ float rowsum[BM];
    const uint32_t sm_base = smem_u32(sm);
    const int tid = threadIdx.x;
    const int warp = tid >> 5, lane = tid & 31;
    const int warp_m = warp >> 1;
    const int warp_n = warp & 1;
    const int nt = blockIdx.x;
    const int mt = blockIdx.y;

    const __half* Ag = d_A2 + (size_t)mt * BM * HH;
    const __half* Bg = d_B2 + (size_t)nt * BN;

    const int a_row0 = tid >> 2;
    const int a_q = tid & 3;
    const int b_row0 = tid >> 4;
    const int b_q = tid & 15;

    if (tid < BM) rowsum[tid] = 0.f;

    float acc[4][8][4];
#pragma unroll
    for (int t = 0; t < 4; t++)
#pragma unroll
        for (int n = 0; n < 8; n++)
#pragma unroll
            for (int j = 0; j < 4; j++) acc[t][n][j] = 0.f;

    auto load_stage = [&](int s, int kb) {
        const uint32_t as = sm_base + s * STAGE_BYTES;
        const uint32_t bs = as + A_BYTES;
#pragma unroll
        for (int j = 0; j < 4; j++) {
            const int row = a_row0 + j * 32;
            cp16(as + row * 80 + a_q * 16,
                 Ag + (size_t)row * HH + kb * BK + a_q * 8);
        }
#pragma unroll
        for (int j = 0; j < 4; j++) {
            const int row = b_row0 + j * 8;
            cp16(bs + row * 272 + b_q * 16,
                 Bg + (size_t)(kb * BK + row) * VV + b_q * 8);
        }
    };

#pragma unroll
    for (int s = 0; s < STAGES - 1; s++) { load_stage(s, s); cp_commit(); }

    for (int it = 0; it < KTILES; it++) {
        cp_wait2();
        __syncthreads();
        if (it + STAGES - 1 < KTILES) load_stage((it + STAGES - 1) & (STAGES - 1), it + STAGES - 1);
        cp_commit();

        const uint32_t as = sm_base + (it & (STAGES - 1)) * STAGE_BYTES;
        const uint32_t bs = as + A_BYTES;
#pragma unroll
        for (int k2 = 0; k2 < 2; k2++) {
            uint32_t af[4][4];
#pragma unroll
            for (int t = 0; t < 4; t++)
                ldm_x4(af[t], as + (warp_m * 64 + t * 16 + (lane & 15)) * 80
                              + k2 * 32 + (lane >> 4) * 16);
            uint32_t bf[4][4];
#pragma unroll
            for (int p = 0; p < 4; p++)
                ldm_x4_t(bf[p], bs + (k2 * 16 + (lane & 15)) * 272
                               + (warp_n * 64 + p * 16 + (lane >> 4) * 8) * 2);
#pragma unroll
            for (int t = 0; t < 4; t++)
#pragma unroll
                for (int n = 0; n < 8; n++)
                    mma16816(acc[t][n], af[t], bf[n >> 1][(n & 1) * 2], bf[n >> 1][(n & 1) * 2 + 1]);
        }
    }

    const int group = lane >> 2, tg = lane & 3;
#pragma unroll
    for (int t = 0; t < 4; t++) {
        const int lr0 = warp_m * 64 + t * 16 + group;
        const int lr1 = lr0 + 8;
        const int r0 = mt * BM + lr0;
        const int r1 = mt * BM + lr1;
        float s0 = 0.f, s1 = 0.f;
#pragma unroll
        for (int n = 0; n < 8; n++) {
            const int col = nt * BN + warp_n * 64 + n * 8 + tg * 2;
            const float2 bv = *(const float2*)(bias + col);
            const float v00 = acc[t][n][0] + bv.x, v01 = acc[t][n][1] + bv.y;
            const float v10 = acc[t][n][2] + bv.x, v11 = acc[t][n][3] + bv.y;
            if (r0 < MMROWS)
                *(__half2*)(d_logits + (size_t)r0 * VV + col) = __floats2half2_rn(v00, v01);
            if (r1 < MMROWS)
                *(__half2*)(d_logits + (size_t)r1 * VV + col) = __floats2half2_rn(v10, v11);
            s0 += __expf(v00) + __expf(v01);
            s1 += __expf(v10) + __expf(v11);
        }
        atomicAdd(&rowsum[lr0], s0);
        atomicAdd(&rowsum[lr1], s1);
    }
    __syncthreads();
    if (tid < BM) {
        const int r = mt * BM + tid;
        if (r < MMROWS) atomicAdd(&d_sumexp[r], rowsum[tid]);
    }
}

// ---------------- blend: vocab-eighth per CTA (16KB smem, 256 thr) ----------------
__global__ __launch_bounds__(256)
void nmt_blend_kernel(const float* __restrict__ weights,
                      const float* __restrict__ p_trans,
                      float* __restrict__ out) {
    extern __shared__ float ts[];               // VQ floats (16 KB)
    const int q = blockIdx.x;                   // 0..7
    const int bt = blockIdx.y;                  // 0..799
    const int b = bt / TT;
    const int tid = threadIdx.x;
    const int vbase = q * VQ;

    const float logZ = __logf(d_sumexp[bt]);
    const float pt = p_trans[bt];
    const float lom = __logf(1.f - pt) - logZ;

    float4* tsv = (float4*)ts;
    const float4 z4 = make_float4(0.f, 0.f, 0.f, 0.f);
    for (int i = tid; i < VQ / 4; i += 256) tsv[i] = z4;   // 1000 float4, guarded
    __syncthreads();

    // scatter from this eighth's bucket (all entries hit; no bounds filter)
    const float* wrow = weights + (size_t)bt * SS;
    const int bq = b * NQ + q;
    const int cnt = d_ccount[bq];
    const uint32_t* cp = d_cpack + (size_t)bq * SS * KK;
    const float* cv = d_cval + (size_t)bq * SS * KK;
    for (int j = tid; j < cnt; j += 256) {
        const uint32_t u = cp[j];
        atomicAdd(&ts[u & 0xFFFu], cv[j] * wrow[u >> 12]);
    }
    __syncthreads();

    // 8 halves per iter: uint4 load of fp16 logits, float4 ts reads, two float4 stores
    const uint4* lrow = (const uint4*)(d_logits + (size_t)bt * VV + vbase);
    float4* orow = (float4*)(out + (size_t)bt * VV + vbase);
    for (int i = tid; i < VQ / 8; i += 256) {              // 500 iters, guarded
        const uint4 lp = lrow[i];
        const __half2 h[4] = {
            *(const __half2*)&lp.x, *(const __half2*)&lp.y,
            *(const __half2*)&lp.z, *(const __half2*)&lp.w
        };
        float le[8];
#pragma unroll
        for (int j = 0; j < 4; j++) {
            const float2 f = __half22float2(h[j]);
            le[j * 2] = f.x; le[j * 2 + 1] = f.y;
        }
        const float4 t0 = tsv[i * 2];
        const float4 t1 = tsv[i * 2 + 1];
        const float te[8] = {t0.x, t0.y, t0.z, t0.w, t1.x, t1.y, t1.z, t1.w};
        float oe[8];
#pragma unroll
        for (int j = 0; j < 8; j++) {
            if (te[j] == 0.f) oe[j] = lom + le[j];
            else oe[j] = __logf(fmaf(pt, te[j], __expf(le[j] + lom)));
        }
        orow[i * 2]     = make_float4(oe[0], oe[1], oe[2], oe[3]);
        orow[i * 2 + 1] = make_float4(oe[4], oe[5], oe[6], oe[7]);
    }
}

// ---------------- launch ----------------
extern "C" void kernel_launch(void* const* d_in, const int* in_sizes, int n_in,
                              void* d_out, int out_size) {
    const float* dec_out     = (const float*)d_in[0];
    const float* W           = (const float*)d_in[1];
    const float* bias        = (const float*)d_in[2];
    const float* weights     = (const float*)d_in[3];
    const float* p_trans     = (const float*)d_in[4];
    const float* trans_probs = (const float*)d_in[5];
    const float* probs       = (const float*)d_in[6];
    const int*   idxes       = (const int*)d_in[7];
    float* out = (float*)d_out;

    zero_accums<<<(MMROWS + 255) / 256, 256>>>();
    compact_kernel<<<BB, 512>>>(trans_probs, probs, idxes);
    conv_a_kernel<<<(MMROWS * 128 + 255) / 256, 256>>>(dec_out);
    conv_b_kernel<<<(CB_TOT / 4 + 255) / 256, 256>>>(W);

    cudaFuncSetAttribute(nmt_gemm_mma, cudaFuncAttributeMaxDynamicSharedMemorySize, GEMM_SMEM);
    nmt_gemm_mma<<<dim3(VV / BN, MPAD / BM), 128, GEMM_SMEM>>>(bias);

    const int blend_smem = VQ * sizeof(float);       // 16000
    cudaFuncSetAttribute(nmt_blend_kernel, cudaFuncAttributeMaxDynamicSharedMemorySize, blend_smem);
    nmt_blend_kernel<<<dim3(NQ, MMROWS), 256, blend_smem>>>(weights, p_trans, out);
}